// round 10
// baseline (speedup 1.0000x reference)
#include <cuda_runtime.h>
#include <cuda_bf16.h>
#include <math.h>
#include <stdint.h>

// ============================================================================
// ODE-RNN: B=128, F=512, I=128, H=512, O=1, NSTEP=5
//
// Pipeline (4 kernel launches, all default-stream, graph-capturable):
//   1) init_kernel     : zero group-barrier counters + h0
//   2) xproj_kernel    : xproj[f][b][h] = x[b,f]@Wih^T + bih + bhh   (parallel)
//   3) odernn_persist  : 128 resident CTAs = 8 batch-groups x 16 col-CTAs,
//                        512 steps x (5 Euler substeps x 2 GEMMs + RNN GEMM),
//                        group-local L2 barrier between dependent GEMMs,
//                        f32x2 packed-FMA inner loops, running mean of h.
//   4) finalize_kernel : out[b] = sigmoid(sum_c partial + bc)  (deterministic)
// ============================================================================

#define BB     128
#define FF     512
#define IDIM   128
#define HH     512
#define NSTEPS 5
#define NG     8     // batch groups
#define BG     16    // samples per group
#define NC     16    // column CTAs per group
#define HC     32    // columns per CTA
#define NTHR   256

// ---------------- device scratch (static: no cudaMalloc allowed) -----------
__device__ float    g_xproj[(size_t)FF * BB * HH];  // 128 MiB
__device__ float    g_h[NG * BG * HH];              // ping buffer for h
__device__ float    g_a[NG * BG * HH];              // relu(h W1^T + b1)
__device__ float    g_part[NC * BB];                // classifier partials
__device__ unsigned g_ctr[NG * 32];                 // padded barrier counters

// ---------------- packed f32x2 helpers --------------------------------------
__device__ __forceinline__ unsigned long long pk2(float x, float y) {
    unsigned long long d;
    asm("mov.b64 %0, {%1, %2};" : "=l"(d) : "f"(x), "f"(y));
    return d;
}
__device__ __forceinline__ unsigned long long fma2(unsigned long long a,
                                                   unsigned long long b,
                                                   unsigned long long c) {
    unsigned long long d;
    asm("fma.rn.f32x2 %0, %1, %2, %3;" : "=l"(d) : "l"(a), "l"(b), "l"(c));
    return d;
}
__device__ __forceinline__ float upsum(unsigned long long v) {
    float lo, hi;
    asm("mov.b64 {%0, %1}, %2;" : "=f"(lo), "=f"(hi) : "l"(v));
    return lo + hi;
}

// ---------------- group barrier (release-add / acquire-spin) ---------------
__device__ __forceinline__ void group_barrier(unsigned* ctr, int tid, unsigned target) {
    __threadfence();      // order this thread's STGs to gpu scope
    __syncthreads();      // all threads' stores+fences done before the add
    if (tid == 0) {
        atomicAdd(ctr, 1u);
        unsigned v;
        do {
            asm volatile("ld.acquire.gpu.global.u32 %0, [%1];"
                         : "=r"(v) : "l"(ctr) : "memory");
        } while (v < target);
    }
    __syncthreads();      // propagate acquire to the block
}

// ---------------- stage 16x512 fp32 tile: global(L2) -> SMEM ---------------
__device__ __forceinline__ void stage_tile(const float* src, float4* dst, int tid) {
    __syncthreads();  // prior readers of dst are done
    const float4* s4 = (const float4*)src;
#pragma unroll
    for (int it = 0; it < 8; ++it)
        dst[tid + it * NTHR] = __ldcg(s4 + tid + it * NTHR);  // .cg: skip stale L1
    __syncthreads();
}

// ---------------- GEMM core: 2 output rows, k=512, packed FMA --------------
__device__ __forceinline__ void gemm_core(const float4* __restrict__ w,
                                          const float4* h0, const float4* h1,
                                          float& s0, float& s1) {
    unsigned long long a00 = 0ull, a01 = 0ull, a10 = 0ull, a11 = 0ull;
#pragma unroll 8
    for (int k = 0; k < HH / 4; ++k) {
        float4 wv = __ldg(w + k);   // weight row (L1-resident after warmup)
        float4 x0 = h0[k];          // SMEM broadcast (all lanes same addr)
        float4 x1 = h1[k];
        unsigned long long wlo = pk2(wv.x, wv.y);
        unsigned long long whi = pk2(wv.z, wv.w);
        a00 = fma2(wlo, pk2(x0.x, x0.y), a00);
        a01 = fma2(whi, pk2(x0.z, x0.w), a01);
        a10 = fma2(wlo, pk2(x1.x, x1.y), a10);
        a11 = fma2(whi, pk2(x1.z, x1.w), a11);
    }
    s0 = upsum(a00) + upsum(a01);
    s1 = upsum(a10) + upsum(a11);
}

// ============================================================================
// 1) init: zero counters and h0
// ============================================================================
__global__ void init_kernel() {
    int t = blockIdx.x * blockDim.x + threadIdx.x;
    if (t < NG * 32) g_ctr[t] = 0u;
    for (int i = t; i < NG * BG * HH; i += gridDim.x * blockDim.x)
        g_h[i] = 0.0f;
}

// ============================================================================
// 2) xproj[f][b][h] = x[b,f,:] @ Wih^T + bih + bhh
//    grid: (B*F/16, H/128), block: 256.  Tile: 16 bf-rows x 128 h-cols.
// ============================================================================
__global__ void __launch_bounds__(256) xproj_kernel(const float* __restrict__ x,
                                                    const float* __restrict__ Wih,
                                                    const float* __restrict__ bih,
                                                    const float* __restrict__ bhh) {
    __shared__ float4 xs[16 * (IDIM / 4)];  // 512 float4 = 8 KB
    const int tid   = threadIdx.x;
    const int m0    = blockIdx.x * 16;                  // bf row base
    const int j     = blockIdx.y * 128 + (tid & 127);   // output column
    const int rbase = (tid >> 7) * 8;                   // 0 or 8

    // x rows are contiguous (I==128): copy 16*128 floats
    const float4* xg = (const float4*)(x + (size_t)m0 * IDIM);
#pragma unroll
    for (int it = 0; it < 2; ++it) xs[tid + it * 256] = xg[tid + it * 256];
    __syncthreads();

    const float4* wr = (const float4*)(Wih + (size_t)j * IDIM);
    float acc[8];
#pragma unroll
    for (int r = 0; r < 8; ++r) acc[r] = 0.0f;

#pragma unroll 4
    for (int k = 0; k < IDIM / 4; ++k) {
        float4 w = __ldg(wr + k);
#pragma unroll
        for (int r = 0; r < 8; ++r) {
            float4 xv = xs[(rbase + r) * (IDIM / 4) + k];
            acc[r] += w.x * xv.x + w.y * xv.y + w.z * xv.z + w.w * xv.w;
        }
    }
    const float bias = __ldg(bih + j) + __ldg(bhh + j);
#pragma unroll
    for (int r = 0; r < 8; ++r) {
        int m = m0 + rbase + r;
        int b = m >> 9;        // m / F
        int f = m & 511;       // m % F
        g_xproj[((size_t)f * BB + b) * HH + j] = acc[r] + bias;
    }
}

// ============================================================================
// 3) persistent recurrence kernel: 128 CTAs (8 groups x 16 col-CTAs)
// ============================================================================
__global__ void __launch_bounds__(NTHR, 1)
odernn_persist(const float* __restrict__ tp,
               const float* __restrict__ W1, const float* __restrict__ b1,
               const float* __restrict__ W2, const float* __restrict__ b2,
               const float* __restrict__ Whh, const float* __restrict__ Wc) {
    __shared__ float4 hbuf[BG * (HH / 4)];  // 32 KB staging tile
    __shared__ float  sc[BG];               // per-sample Euler scale

    const int tid  = threadIdx.x;
    const int g    = blockIdx.x >> 4;   // batch group
    const int c    = blockIdx.x & 15;   // column block
    const int lane = tid & 31;
    const int r0   = (tid >> 5) << 1;   // 2 rows per thread
    const int r1   = r0 + 1;
    const int j    = c * HC + lane;     // output column in [0,512)

    float*    hg  = g_h + g * BG * HH;
    float*    ag  = g_a + g * BG * HH;
    unsigned* ctr = &g_ctr[g * 32];

    const float4* w1r = (const float4*)(W1 + (size_t)j * HH);
    const float4* w2r = (const float4*)(W2 + (size_t)j * HH);
    const float4* whr = (const float4*)(Whh + (size_t)j * HH);
    const float   b1j = __ldg(b1 + j);
    const float   b2j = __ldg(b2 + j);

    const float4* hb0 = hbuf + r0 * (HH / 4);
    const float4* hb1 = hbuf + r1 * (HH / 4);

    float hown0 = 0.0f, hown1 = 0.0f;   // this CTA's 2 elements of h
    float fs0 = 0.0f, fs1 = 0.0f;       // running sum for mean over f
    unsigned nsync = 0;

    for (int f = 0; f < FF; ++f) {
        if (tid < BG) {
            int b   = g * BG + tid;
            float d = (f == 0) ? 0.0f : (tp[b * FF + f] - tp[b * FF + f - 1]);
            sc[tid] = d * (1.0f / NSTEPS);
        }
        // (sc is consumed only after the next stage_tile's __syncthreads)

        for (int s = 0; s < NSTEPS; ++s) {
            // ---- GEMM A: a = relu(h @ W1^T + b1) ----
            stage_tile(hg, hbuf, tid);
            float s0, s1;
            gemm_core(w1r, hb0, hb1, s0, s1);
            ag[r0 * HH + j] = fmaxf(s0 + b1j, 0.0f);
            ag[r1 * HH + j] = fmaxf(s1 + b1j, 0.0f);
            group_barrier(ctr, tid, (++nsync) * NC);

            // ---- GEMM B: h += (a @ W2^T + b2) * scale ----
            stage_tile(ag, hbuf, tid);
            gemm_core(w2r, hb0, hb1, s0, s1);
            hown0 += (s0 + b2j) * sc[r0];
            hown1 += (s1 + b2j) * sc[r1];
            hg[r0 * HH + j] = hown0;
            hg[r1 * HH + j] = hown1;
            group_barrier(ctr, tid, (++nsync) * NC);
        }

        // ---- GEMM C: h = tanh(xproj + hp @ Whh^T) ----
        stage_tile(hg, hbuf, tid);
        {
            float s0, s1;
            gemm_core(whr, hb0, hb1, s0, s1);
            const float* xp = g_xproj + ((size_t)f * BB + g * BG) * HH;
            hown0 = tanhf(s0 + xp[r0 * HH + j]);
            hown1 = tanhf(s1 + xp[r1 * HH + j]);
            fs0 += hown0;
            fs1 += hown1;
            hg[r0 * HH + j] = hown0;
            hg[r1 * HH + j] = hown1;
        }
        group_barrier(ctr, tid, (++nsync) * NC);
    }

    // ---- classifier partial: p[b] += mean_h * Wc[h] over this CTA's cols ----
    const float wcj = __ldg(Wc + j);
    float p0 = fs0 * wcj * (1.0f / FF);
    float p1 = fs1 * wcj * (1.0f / FF);
#pragma unroll
    for (int o = 16; o; o >>= 1) {
        p0 += __shfl_xor_sync(0xffffffffu, p0, o);
        p1 += __shfl_xor_sync(0xffffffffu, p1, o);
    }
    if (lane == 0) {
        g_part[c * BB + g * BG + r0] = p0;
        g_part[c * BB + g * BG + r1] = p1;
    }
}

// ============================================================================
// 4) finalize: out[b] = sigmoid(sum_c part[c][b] + bc)   (deterministic order)
// ============================================================================
__global__ void finalize_kernel(const float* __restrict__ bc, float* __restrict__ out) {
    int b = threadIdx.x;  // 128 threads
    float s = __ldg(bc);
#pragma unroll
    for (int c = 0; c < NC; ++c) s += g_part[c * BB + b];
    out[b] = 1.0f / (1.0f + expf(-s));
}

// ============================================================================
extern "C" void kernel_launch(void* const* d_in, const int* in_sizes, int n_in,
                              void* d_out, int out_size) {
    const float* x   = (const float*)d_in[0];
    const float* tp  = (const float*)d_in[1];
    const float* W1  = (const float*)d_in[2];
    const float* b1  = (const float*)d_in[3];
    const float* W2  = (const float*)d_in[4];
    const float* b2  = (const float*)d_in[5];
    const float* Wih = (const float*)d_in[6];
    const float* Whh = (const float*)d_in[7];
    const float* bih = (const float*)d_in[8];
    const float* bhh = (const float*)d_in[9];
    const float* Wc  = (const float*)d_in[10];
    const float* bc  = (const float*)d_in[11];
    float* out = (float*)d_out;

    init_kernel<<<64, 256>>>();

    dim3 gx(BB * FF / 16, HH / 128);  // (4096, 4)
    xproj_kernel<<<gx, 256>>>(x, Wih, bih, bhh);

    odernn_persist<<<NG * NC, NTHR>>>(tp, W1, b1, W2, b2, Whh, Wc);

    finalize_kernel<<<1, BB>>>(bc, out);

    (void)in_sizes; (void)n_in; (void)out_size;
}

// round 11
// speedup vs baseline: 1.0007x; 1.0007x over previous
#include <cuda_runtime.h>
#include <cuda_bf16.h>
#include <math.h>
#include <stdint.h>

// ============================================================================
// ODE-RNN: B=128, F=512, I=128, H=512, O=1, NSTEP=5
//
// R11 changes vs R10 (123.7 ms):
//  * group barrier: __threadfence+atomicAdd+ld.acquire  ->  per-warp
//    red.release.gpu + relaxed spin.  No MEMBAR.GPU, no CCTL.IVALL:
//    the 192 KB/CTA weight set stays L1-resident across all 5632 phases.
//  * all cross-CTA data traffic is L2-direct (.cg loads / .cg stores);
//    xproj/tp loads are .cg so they cannot evict weights from L1.
//  * inner GEMM loop: ulonglong2 loads feed fma.rn.f32x2 directly
//    (7 instr / k-iter instead of 13; no mov.b64 packing).
//  * removed redundant __syncthreads in stage_tile.
//  * pad launch prepended so ncu's capture window lands on odernn_persist.
// ============================================================================

#define BB     128
#define FF     512
#define IDIM   128
#define HH     512
#define NSTEPS 5
#define NG     8     // batch groups
#define BG     16    // samples per group
#define NC     16    // column CTAs per group
#define HC     32    // columns per CTA
#define NTHR   256
#define WARPS_PER_CTA (NTHR / 32)

// ---------------- device scratch (no cudaMalloc allowed) -------------------
__device__ float    g_xproj[(size_t)FF * BB * HH];  // 128 MiB
__device__ float    g_h[NG * BG * HH];
__device__ float    g_a[NG * BG * HH];
__device__ float    g_part[NC * BB];
__device__ unsigned g_ctr[NG * 32];                 // padded counters

// ---------------- packed f32x2 helpers -------------------------------------
__device__ __forceinline__ unsigned long long fma2(unsigned long long a,
                                                   unsigned long long b,
                                                   unsigned long long c) {
    unsigned long long d;
    asm("fma.rn.f32x2 %0, %1, %2, %3;" : "=l"(d) : "l"(a), "l"(b), "l"(c));
    return d;
}
__device__ __forceinline__ float upsum(unsigned long long v) {
    float lo, hi;
    asm("mov.b64 {%0, %1}, %2;" : "=f"(lo), "=f"(hi) : "l"(v));
    return lo + hi;
}

// ---------------- flush-free group barrier ----------------------------------
// Arrival: one release-red per warp (cumulative over __syncwarp -> orders all
// lanes' prior stores at gpu scope, encoded in the atomic, no L1 flush).
// Wait: thread 0 spins with a relaxed L2 load; consumers read shared data
// exclusively via .cg (L2-direct), so no acquire/invalidate is needed.
__device__ __forceinline__ void group_barrier(unsigned* ctr, int tid, unsigned target) {
    __syncwarp();
    if ((tid & 31) == 0)
        asm volatile("red.release.gpu.global.add.u32 [%0], 1;" :: "l"(ctr) : "memory");
    if (tid == 0) {
        unsigned v;
        do {
            asm volatile("ld.relaxed.gpu.global.u32 %0, [%1];"
                         : "=r"(v) : "l"(ctr) : "memory");
        } while (v < target);
    }
    __syncthreads();
}

// ---------------- stage 16x512 fp32 tile: L2 -> SMEM ------------------------
// Caller guarantees a __syncthreads-equivalent happened since the last reader
// of dst (every call site follows a group_barrier or is the first use).
__device__ __forceinline__ void stage_tile(const float* src, float4* dst, int tid) {
    const float4* s4 = (const float4*)src;
#pragma unroll
    for (int it = 0; it < 8; ++it)
        dst[tid + it * NTHR] = __ldcg(s4 + tid + it * NTHR);
    __syncthreads();
}

// ---------------- GEMM core: 2 output rows, k=512, packed FMA ---------------
__device__ __forceinline__ void gemm_core(const ulonglong2* __restrict__ w,
                                          const ulonglong2* h0, const ulonglong2* h1,
                                          float& s0, float& s1) {
    unsigned long long a00 = 0ull, a01 = 0ull, a10 = 0ull, a11 = 0ull;
#pragma unroll 8
    for (int k = 0; k < HH / 4; ++k) {
        ulonglong2 wv = __ldg(w + k);    // 16B weight row chunk (L1-resident)
        ulonglong2 x0 = h0[k];           // warp-uniform LDS.128 (broadcast)
        ulonglong2 x1 = h1[k];
        a00 = fma2(wv.x, x0.x, a00);
        a01 = fma2(wv.y, x0.y, a01);
        a10 = fma2(wv.x, x1.x, a10);
        a11 = fma2(wv.y, x1.y, a11);
    }
    s0 = upsum(a00) + upsum(a01);
    s1 = upsum(a10) + upsum(a11);
}

// ============================================================================
// 0) pad: no-op launch so ncu's skip-window captures odernn_persist
// ============================================================================
__global__ void pad_kernel() {
    if (threadIdx.x > 1024) g_ctr[0] = 1u;  // never true; keeps launch alive
}

// ============================================================================
// 1) init: zero counters and h0
// ============================================================================
__global__ void init_kernel() {
    int t = blockIdx.x * blockDim.x + threadIdx.x;
    if (t < NG * 32) g_ctr[t] = 0u;
    for (int i = t; i < NG * BG * HH; i += gridDim.x * blockDim.x)
        g_h[i] = 0.0f;
}

// ============================================================================
// 2) xproj[f][b][h] = x[b,f,:] @ Wih^T + bih + bhh
// ============================================================================
__global__ void __launch_bounds__(256) xproj_kernel(const float* __restrict__ x,
                                                    const float* __restrict__ Wih,
                                                    const float* __restrict__ bih,
                                                    const float* __restrict__ bhh) {
    __shared__ float4 xs[16 * (IDIM / 4)];
    const int tid   = threadIdx.x;
    const int m0    = blockIdx.x * 16;
    const int j     = blockIdx.y * 128 + (tid & 127);
    const int rbase = (tid >> 7) * 8;

    const float4* xg = (const float4*)(x + (size_t)m0 * IDIM);
#pragma unroll
    for (int it = 0; it < 2; ++it) xs[tid + it * 256] = xg[tid + it * 256];
    __syncthreads();

    const float4* wr = (const float4*)(Wih + (size_t)j * IDIM);
    float acc[8];
#pragma unroll
    for (int r = 0; r < 8; ++r) acc[r] = 0.0f;

#pragma unroll 4
    for (int k = 0; k < IDIM / 4; ++k) {
        float4 w = __ldg(wr + k);
#pragma unroll
        for (int r = 0; r < 8; ++r) {
            float4 xv = xs[(rbase + r) * (IDIM / 4) + k];
            acc[r] += w.x * xv.x + w.y * xv.y + w.z * xv.z + w.w * xv.w;
        }
    }
    const float bias = __ldg(bih + j) + __ldg(bhh + j);
#pragma unroll
    for (int r = 0; r < 8; ++r) {
        int m = m0 + rbase + r;
        int b = m >> 9;
        int f = m & 511;
        g_xproj[((size_t)f * BB + b) * HH + j] = acc[r] + bias;
    }
}

// ============================================================================
// 3) persistent recurrence: 128 CTAs (8 groups x 16 col-CTAs)
// ============================================================================
__global__ void __launch_bounds__(NTHR, 1)
odernn_persist(const float* __restrict__ tp,
               const float* __restrict__ W1, const float* __restrict__ b1,
               const float* __restrict__ W2, const float* __restrict__ b2,
               const float* __restrict__ Whh, const float* __restrict__ Wc) {
    __shared__ float4 hbuf[BG * (HH / 4)];  // 32 KB
    __shared__ float  sc[BG];

    const int tid  = threadIdx.x;
    const int g    = blockIdx.x >> 4;
    const int c    = blockIdx.x & 15;
    const int lane = tid & 31;
    const int r0   = (tid >> 5) << 1;
    const int r1   = r0 + 1;
    const int j    = c * HC + lane;

    float*    hg  = g_h + g * BG * HH;
    float*    ag  = g_a + g * BG * HH;
    unsigned* ctr = &g_ctr[g * 32];

    const ulonglong2* w1r = (const ulonglong2*)(W1 + (size_t)j * HH);
    const ulonglong2* w2r = (const ulonglong2*)(W2 + (size_t)j * HH);
    const ulonglong2* whr = (const ulonglong2*)(Whh + (size_t)j * HH);
    const float       b1j = __ldg(b1 + j);
    const float       b2j = __ldg(b2 + j);

    const ulonglong2* hb0 = (const ulonglong2*)(hbuf + r0 * (HH / 4));
    const ulonglong2* hb1 = (const ulonglong2*)(hbuf + r1 * (HH / 4));

    float hown0 = 0.0f, hown1 = 0.0f;
    float fs0 = 0.0f, fs1 = 0.0f;
    unsigned nsync = 0;
    const unsigned BAR = NC * WARPS_PER_CTA;  // arrivals per barrier

    for (int f = 0; f < FF; ++f) {
        if (tid < BG) {
            int b   = g * BG + tid;
            float d = (f == 0) ? 0.0f
                               : (__ldcg(tp + b * FF + f) - __ldcg(tp + b * FF + f - 1));
            sc[tid] = d * (1.0f / NSTEPS);
        }
        // sc consumed only after the next stage_tile's __syncthreads

        for (int s = 0; s < NSTEPS; ++s) {
            // ---- GEMM A: a = relu(h @ W1^T + b1) ----
            stage_tile(hg, hbuf, tid);
            float s0, s1;
            gemm_core(w1r, hb0, hb1, s0, s1);
            __stcg(ag + r0 * HH + j, fmaxf(s0 + b1j, 0.0f));
            __stcg(ag + r1 * HH + j, fmaxf(s1 + b1j, 0.0f));
            group_barrier(ctr, tid, (++nsync) * BAR);

            // ---- GEMM B: h += (a @ W2^T + b2) * scale ----
            stage_tile(ag, hbuf, tid);
            gemm_core(w2r, hb0, hb1, s0, s1);
            hown0 += (s0 + b2j) * sc[r0];
            hown1 += (s1 + b2j) * sc[r1];
            __stcg(hg + r0 * HH + j, hown0);
            __stcg(hg + r1 * HH + j, hown1);
            group_barrier(ctr, tid, (++nsync) * BAR);
        }

        // ---- GEMM C: h = tanh(xproj + hp @ Whh^T) ----
        {
            // issue xproj loads early (DRAM-latency, hidden under the GEMM)
            const float* xp = g_xproj + ((size_t)f * BB + g * BG) * HH;
            float xp0 = __ldcg(xp + r0 * HH + j);
            float xp1 = __ldcg(xp + r1 * HH + j);
            stage_tile(hg, hbuf, tid);
            float s0, s1;
            gemm_core(whr, hb0, hb1, s0, s1);
            hown0 = tanhf(s0 + xp0);
            hown1 = tanhf(s1 + xp1);
            fs0 += hown0;
            fs1 += hown1;
            __stcg(hg + r0 * HH + j, hown0);
            __stcg(hg + r1 * HH + j, hown1);
        }
        group_barrier(ctr, tid, (++nsync) * BAR);
    }

    // ---- classifier partials over this CTA's 32 columns ----
    const float wcj = __ldg(Wc + j);
    float p0 = fs0 * wcj * (1.0f / FF);
    float p1 = fs1 * wcj * (1.0f / FF);
#pragma unroll
    for (int o = 16; o; o >>= 1) {
        p0 += __shfl_xor_sync(0xffffffffu, p0, o);
        p1 += __shfl_xor_sync(0xffffffffu, p1, o);
    }
    if (lane == 0) {
        g_part[c * BB + g * BG + r0] = p0;
        g_part[c * BB + g * BG + r1] = p1;
    }
}

// ============================================================================
// 4) finalize: out[b] = sigmoid(sum_c part[c][b] + bc)
// ============================================================================
__global__ void finalize_kernel(const float* __restrict__ bc, float* __restrict__ out) {
    int b = threadIdx.x;
    float s = __ldg(bc);
#pragma unroll
    for (int c = 0; c < NC; ++c) s += g_part[c * BB + b];
    out[b] = 1.0f / (1.0f + expf(-s));
}

// ============================================================================
extern "C" void kernel_launch(void* const* d_in, const int* in_sizes, int n_in,
                              void* d_out, int out_size) {
    const float* x   = (const float*)d_in[0];
    const float* tp  = (const float*)d_in[1];
    const float* W1  = (const float*)d_in[2];
    const float* b1  = (const float*)d_in[3];
    const float* W2  = (const float*)d_in[4];
    const float* b2  = (const float*)d_in[5];
    const float* Wih = (const float*)d_in[6];
    const float* Whh = (const float*)d_in[7];
    const float* bih = (const float*)d_in[8];
    const float* bhh = (const float*)d_in[9];
    const float* Wc  = (const float*)d_in[10];
    const float* bc  = (const float*)d_in[11];
    float* out = (float*)d_out;

    pad_kernel<<<1, 32>>>();   // shifts ncu capture window onto odernn_persist

    init_kernel<<<64, 256>>>();

    dim3 gx(BB * FF / 16, HH / 128);
    xproj_kernel<<<gx, 256>>>(x, Wih, bih, bhh);

    odernn_persist<<<NG * NC, NTHR>>>(tp, W1, b1, W2, b2, Whh, Wc);

    finalize_kernel<<<1, BB>>>(bc, out);

    (void)in_sizes; (void)n_in; (void)out_size;
}

// round 12
// speedup vs baseline: 5.6461x; 5.6424x over previous
#include <cuda_runtime.h>
#include <cuda_bf16.h>
#include <math.h>
#include <stdint.h>

// ============================================================================
// ODE-RNN: B=128, F=512, I=128, H=512, O=1, NSTEP=5
//
// R12 vs R11 (123.6 ms, L1tex-wavefront bound on uncoalesced weight LDG):
//  * W1/W2 weight k-slices held in REGISTERS (64 floats/matrix/thread as
//    f32x2 pairs) -> zero weight memory traffic in the hot loop.
//  * warp owns (all 16 rows x 32 cols x 64-wide k-slice); split-k over the
//    8 warps, combined by a conflict-free SMEM tree reduction per GEMM.
//  * Whh in SMEM (k4-chunked, conflict-free LDS.128) -- used 1 of 11 phases.
//  * hot loop = broadcast LDS.128 (h) + fma.rn.f32x2 only.
//  * barrier: flush-free red.release.gpu + relaxed spin (from R11).
// ============================================================================

#define BB     128
#define FF     512
#define IDIM   128
#define HH     512
#define NSTEPS 5
#define NG     8     // batch groups
#define BG     16    // samples per group
#define NC     16    // column CTAs per group
#define HC     32    // columns per CTA
#define NTHR   256
#define WPC    8     // warps per CTA
#define KW     64    // k-slice width per warp
#define BARN   (NC * WPC)   // barrier arrivals per phase

// ---------------- device scratch (no cudaMalloc allowed) -------------------
__device__ float    g_xproj[(size_t)FF * BB * HH];  // 128 MiB
__device__ float    g_h[NG * BG * HH];
__device__ float    g_a[NG * BG * HH];
__device__ float    g_part[NC * BB];
__device__ unsigned g_ctr[NG * 32];

// ---------------- dynamic SMEM layout (float offsets) ----------------------
//  hbuf  [BG*HH]              32 KB   staged activation tile
//  whhs  [(HH/4)*HC*4]        64 KB   Whh slice, k4-chunked
//  red   [BG*WPC*HC]          16 KB   split-k reduction
//  sc    [BG]                 64 B    per-sample Euler scale
#define SM_HBUF 0
#define SM_WHH  (BG * HH)                     // 8192
#define SM_RED  (SM_WHH + (HH / 4) * HC * 4)  // 24576
#define SM_SC   (SM_RED + BG * WPC * HC)      // 28672
#define SM_TOT  ((SM_SC + BG) * 4)            // 114,752 bytes

// ---------------- packed f32x2 helpers -------------------------------------
__device__ __forceinline__ unsigned long long fma2(unsigned long long a,
                                                   unsigned long long b,
                                                   unsigned long long c) {
    unsigned long long d;
    asm("fma.rn.f32x2 %0, %1, %2, %3;" : "=l"(d) : "l"(a), "l"(b), "l"(c));
    return d;
}
__device__ __forceinline__ float upsum(unsigned long long v) {
    float lo, hi;
    asm("mov.b64 {%0, %1}, %2;" : "=f"(lo), "=f"(hi) : "l"(v));
    return lo + hi;
}

// ---------------- flush-free group barrier ----------------------------------
__device__ __forceinline__ void group_barrier(unsigned* ctr, int tid, unsigned target) {
    __syncwarp();
    if ((tid & 31) == 0)
        asm volatile("red.release.gpu.global.add.u32 [%0], 1;" :: "l"(ctr) : "memory");
    if (tid == 0) {
        unsigned v;
        do {
            asm volatile("ld.relaxed.gpu.global.u32 %0, [%1];"
                         : "=r"(v) : "l"(ctr) : "memory");
        } while (v < target);
    }
    __syncthreads();
}

// ---------------- stage 16x512 fp32 tile: L2 -> SMEM ------------------------
__device__ __forceinline__ void stage_tile(const float* src, float* dstf, int tid) {
    const float4* s4 = (const float4*)src;
    float4*       d4 = (float4*)dstf;
#pragma unroll
    for (int it = 0; it < 8; ++it)
        d4[tid + it * NTHR] = __ldcg(s4 + tid + it * NTHR);
    __syncthreads();
}

// ---------------- GEMM, weights in registers --------------------------------
// warp computes: part[r] = sum_{k in [k0,k0+64)} W[j][k] * h[r][k], r=0..15
__device__ __forceinline__ void gemm_w_reg(const unsigned long long wreg[KW / 2],
                                           const float* __restrict__ hb, int k0,
                                           float part[BG]) {
    unsigned long long acc[BG];
#pragma unroll
    for (int r = 0; r < BG; ++r) acc[r] = 0ull;
#pragma unroll
    for (int k4 = 0; k4 < KW / 4; ++k4) {
#pragma unroll
        for (int r = 0; r < BG; ++r) {
            ulonglong2 hv = *(const ulonglong2*)(hb + r * HH + k0 + 4 * k4);
            acc[r] = fma2(wreg[2 * k4],     hv.x, acc[r]);
            acc[r] = fma2(wreg[2 * k4 + 1], hv.y, acc[r]);
        }
    }
#pragma unroll
    for (int r = 0; r < BG; ++r) part[r] = upsum(acc[r]);
}

// ---------------- GEMM, weights in SMEM (Whh) -------------------------------
__device__ __forceinline__ void gemm_w_smem(const float* __restrict__ wsm,
                                            int w, int l,
                                            const float* __restrict__ hb, int k0,
                                            float part[BG]) {
    unsigned long long acc[BG];
#pragma unroll
    for (int r = 0; r < BG; ++r) acc[r] = 0ull;
#pragma unroll
    for (int k4 = 0; k4 < KW / 4; ++k4) {
        // chunk (k4g, lane): conflict-free LDS.128 (lanes consecutive 16B)
        ulonglong2 wv = *(const ulonglong2*)(wsm + (((w * 16 + k4) * HC + l) << 2));
#pragma unroll
        for (int r = 0; r < BG; ++r) {
            ulonglong2 hv = *(const ulonglong2*)(hb + r * HH + k0 + 4 * k4);
            acc[r] = fma2(wv.x, hv.x, acc[r]);
            acc[r] = fma2(wv.y, hv.y, acc[r]);
        }
    }
#pragma unroll
    for (int r = 0; r < BG; ++r) part[r] = upsum(acc[r]);
}

// ---------------- split-k reduction over 8 warps -----------------------------
__device__ __forceinline__ void reduce_k(float* red, const float part[BG],
                                         int w, int l, float& s0, float& s1) {
#pragma unroll
    for (int r = 0; r < BG; ++r)
        red[(r * WPC + w) * HC + l] = part[r];   // conflict-free STS.32
    __syncthreads();
    const int r0 = 2 * w, r1 = r0 + 1;
    s0 = 0.0f; s1 = 0.0f;
#pragma unroll
    for (int wp = 0; wp < WPC; ++wp) {
        s0 += red[(r0 * WPC + wp) * HC + l];
        s1 += red[(r1 * WPC + wp) * HC + l];
    }
}

// ============================================================================
__global__ void pad_kernel() {
    if (threadIdx.x > 1024) g_ctr[0] = 1u;  // never true
}

__global__ void init_kernel() {
    int t = blockIdx.x * blockDim.x + threadIdx.x;
    if (t < NG * 32) g_ctr[t] = 0u;
    for (int i = t; i < NG * BG * HH; i += gridDim.x * blockDim.x)
        g_h[i] = 0.0f;
}

// ============================================================================
// xproj[f][b][h] = x[b,f,:] @ Wih^T + bih + bhh
// ============================================================================
__global__ void __launch_bounds__(256) xproj_kernel(const float* __restrict__ x,
                                                    const float* __restrict__ Wih,
                                                    const float* __restrict__ bih,
                                                    const float* __restrict__ bhh) {
    __shared__ float4 xs[16 * (IDIM / 4)];
    const int tid   = threadIdx.x;
    const int m0    = blockIdx.x * 16;
    const int j     = blockIdx.y * 128 + (tid & 127);
    const int rbase = (tid >> 7) * 8;

    const float4* xg = (const float4*)(x + (size_t)m0 * IDIM);
#pragma unroll
    for (int it = 0; it < 2; ++it) xs[tid + it * 256] = xg[tid + it * 256];
    __syncthreads();

    const float4* wr = (const float4*)(Wih + (size_t)j * IDIM);
    float acc[8];
#pragma unroll
    for (int r = 0; r < 8; ++r) acc[r] = 0.0f;

#pragma unroll 4
    for (int k = 0; k < IDIM / 4; ++k) {
        float4 w = __ldg(wr + k);
#pragma unroll
        for (int r = 0; r < 8; ++r) {
            float4 xv = xs[(rbase + r) * (IDIM / 4) + k];
            acc[r] += w.x * xv.x + w.y * xv.y + w.z * xv.z + w.w * xv.w;
        }
    }
    const float bias = __ldg(bih + j) + __ldg(bhh + j);
#pragma unroll
    for (int r = 0; r < 8; ++r) {
        int m = m0 + rbase + r;
        int b = m >> 9;
        int f = m & 511;
        g_xproj[((size_t)f * BB + b) * HH + j] = acc[r] + bias;
    }
}

// ============================================================================
// persistent recurrence: 128 CTAs (8 groups x 16 col-CTAs)
// ============================================================================
__global__ void __launch_bounds__(NTHR, 1)
odernn_persist(const float* __restrict__ tp,
               const float* __restrict__ W1, const float* __restrict__ b1,
               const float* __restrict__ W2, const float* __restrict__ b2,
               const float* __restrict__ Whh, const float* __restrict__ Wc) {
    extern __shared__ float smem[];
    float* hbuf = smem + SM_HBUF;
    float* whhs = smem + SM_WHH;
    float* red  = smem + SM_RED;
    float* sc   = smem + SM_SC;

    const int tid  = threadIdx.x;
    const int g    = blockIdx.x >> 4;
    const int cblk = blockIdx.x & 15;
    const int w    = tid >> 5;        // warp id = k-slice
    const int l    = tid & 31;        // lane = column
    const int j    = cblk * HC + l;   // global output column
    const int k0   = w * KW;          // this warp's k-slice base
    const int r0   = 2 * w, r1 = r0 + 1;  // rows this thread owns post-reduce

    float*    hg  = g_h + g * BG * HH;
    float*    ag  = g_a + g * BG * HH;
    unsigned* ctr = &g_ctr[g * 32];

    // ---- load W1/W2 k-slices into registers (f32x2 pairs), once ----
    unsigned long long w1r[KW / 2], w2r[KW / 2];
#pragma unroll
    for (int i = 0; i < KW / 2; ++i) {
        w1r[i] = *(const unsigned long long*)(W1 + (size_t)j * HH + k0 + 2 * i);
        w2r[i] = *(const unsigned long long*)(W2 + (size_t)j * HH + k0 + 2 * i);
    }
    // ---- Whh slice -> SMEM (k4-chunked) ----
#pragma unroll
    for (int i = 0; i < 16; ++i) {
        int k4g = w * 16 + i;
        float4 v = *(const float4*)(Whh + (size_t)j * HH + 4 * k4g);
        *(float4*)(whhs + ((k4g * HC + l) << 2)) = v;
    }
    const float b1j = __ldg(b1 + j);
    const float b2j = __ldg(b2 + j);
    __syncthreads();

    float hown0 = 0.0f, hown1 = 0.0f;
    float fs0 = 0.0f, fs1 = 0.0f;
    unsigned nsync = 0;
    float part[BG];
    float s0, s1;

    for (int f = 0; f < FF; ++f) {
        if (tid < BG) {
            int b   = g * BG + tid;
            float d = (f == 0) ? 0.0f
                               : (__ldcg(tp + b * FF + f) - __ldcg(tp + b * FF + f - 1));
            sc[tid] = d * (1.0f / NSTEPS);
        }
        // sc published by the next stage_tile's __syncthreads

        for (int s = 0; s < NSTEPS; ++s) {
            // ---- GEMM A: a = relu(h @ W1^T + b1) ----
            stage_tile(hg, hbuf, tid);
            gemm_w_reg(w1r, hbuf, k0, part);
            reduce_k(red, part, w, l, s0, s1);
            __stcg(ag + r0 * HH + j, fmaxf(s0 + b1j, 0.0f));
            __stcg(ag + r1 * HH + j, fmaxf(s1 + b1j, 0.0f));
            group_barrier(ctr, tid, (++nsync) * BARN);

            // ---- GEMM B: h += (a @ W2^T + b2) * scale ----
            stage_tile(ag, hbuf, tid);
            gemm_w_reg(w2r, hbuf, k0, part);
            reduce_k(red, part, w, l, s0, s1);
            hown0 += (s0 + b2j) * sc[r0];
            hown1 += (s1 + b2j) * sc[r1];
            __stcg(hg + r0 * HH + j, hown0);
            __stcg(hg + r1 * HH + j, hown1);
            group_barrier(ctr, tid, (++nsync) * BARN);
        }

        // ---- GEMM C: h = tanh(xproj + hp @ Whh^T) ----
        {
            const float* xp = g_xproj + ((size_t)f * BB + g * BG) * HH;
            float xp0 = __ldcg(xp + r0 * HH + j);
            float xp1 = __ldcg(xp + r1 * HH + j);
            stage_tile(hg, hbuf, tid);
            gemm_w_smem(whhs, w, l, hbuf, k0, part);
            reduce_k(red, part, w, l, s0, s1);
            hown0 = tanhf(s0 + xp0);
            hown1 = tanhf(s1 + xp1);
            fs0 += hown0;
            fs1 += hown1;
            __stcg(hg + r0 * HH + j, hown0);
            __stcg(hg + r1 * HH + j, hown1);
        }
        group_barrier(ctr, tid, (++nsync) * BARN);
    }

    // ---- classifier partials over this CTA's 32 columns ----
    const float wcj = __ldg(Wc + j);
    float p0 = fs0 * wcj * (1.0f / FF);
    float p1 = fs1 * wcj * (1.0f / FF);
#pragma unroll
    for (int o = 16; o; o >>= 1) {
        p0 += __shfl_xor_sync(0xffffffffu, p0, o);
        p1 += __shfl_xor_sync(0xffffffffu, p1, o);
    }
    if (l == 0) {
        g_part[cblk * BB + g * BG + r0] = p0;
        g_part[cblk * BB + g * BG + r1] = p1;
    }
}

// ============================================================================
__global__ void finalize_kernel(const float* __restrict__ bc, float* __restrict__ out) {
    int b = threadIdx.x;
    float s = __ldg(bc);
#pragma unroll
    for (int c = 0; c < NC; ++c) s += g_part[c * BB + b];
    out[b] = 1.0f / (1.0f + expf(-s));
}

// ============================================================================
extern "C" void kernel_launch(void* const* d_in, const int* in_sizes, int n_in,
                              void* d_out, int out_size) {
    const float* x   = (const float*)d_in[0];
    const float* tp  = (const float*)d_in[1];
    const float* W1  = (const float*)d_in[2];
    const float* b1  = (const float*)d_in[3];
    const float* W2  = (const float*)d_in[4];
    const float* b2  = (const float*)d_in[5];
    const float* Wih = (const float*)d_in[6];
    const float* Whh = (const float*)d_in[7];
    const float* bih = (const float*)d_in[8];
    const float* bhh = (const float*)d_in[9];
    const float* Wc  = (const float*)d_in[10];
    const float* bc  = (const float*)d_in[11];
    float* out = (float*)d_out;

    cudaFuncSetAttribute(odernn_persist,
                         cudaFuncAttributeMaxDynamicSharedMemorySize, SM_TOT);

    pad_kernel<<<1, 32>>>();   // keeps ncu capture window on odernn_persist

    init_kernel<<<64, 256>>>();

    dim3 gx(BB * FF / 16, HH / 128);
    xproj_kernel<<<gx, 256>>>(x, Wih, bih, bhh);

    odernn_persist<<<NG * NC, NTHR, SM_TOT>>>(tp, W1, b1, W2, b2, Whh, Wc);

    finalize_kernel<<<1, BB>>>(bc, out);

    (void)in_sizes; (void)n_in; (void)out_size;
}